// round 13
// baseline (speedup 1.0000x reference)
#include <cuda_runtime.h>
#include <math.h>

#define NTOK 32768
#define NBLK 16           // persistent grid for attn stack (all resident)

// flash smem layout (floats)
#define OFF_K 0               // [64][68]
#define OFF_V 4352            // [64][68]
#define OFF_S 8704            // scores/probs [64 keys][36] (32 rows + pad)
#define OFF_Q 11008           // [32][68]
#define OFF_CORR 13184        // [32]
#define OFF_LINV 13216        // [32]
#define SMEM_FLOATS 13248
#define SMEM_BYTES (SMEM_FLOATS * 4)

// ---------------- scratch (static device memory; no allocation) ----------------
__device__ float g_t  [NTOK * 64];
__device__ float g_hT [NTOK * 64];
__device__ float g_qs [NTOK * 64];
__device__ float g_ks [NTOK * 64];
__device__ float g_vs [NTOK * 64];
__device__ int   g_idx3[3 * NTOK];
__device__ int   g_M3[3];
__device__ unsigned g_gen = 0;
__device__ unsigned g_arrive = 0;

// ---------------- software grid barrier ----------------------------------------
__device__ __forceinline__ void grid_bar()
{
    __syncthreads();
    if (threadIdx.x == 0) {
        __threadfence();
        unsigned gen = *(volatile unsigned*)&g_gen;
        if (atomicAdd(&g_arrive, 1u) == NBLK - 1) {
            g_arrive = 0;
            __threadfence();
            atomicAdd(&g_gen, 1u);
        } else {
            while (*(volatile unsigned*)&g_gen == gen) {}
        }
        __threadfence();
    }
    __syncthreads();
}

// ---------------- dilation index build (ss-table, bit-exact vs numpy) ----------
__global__ void __launch_bounds__(256) build_idx_kernel()
{
    __shared__ unsigned char valid[769];
    __shared__ int scan[256];
    int bi  = blockIdx.x;
    int dil = (bi == 0) ? 2 : (bi == 1) ? 4 : 6;
    int* out = g_idx3 + bi * NTOK;
    int tid  = threadIdx.x;
    float fd = (float)dil;

    for (int ss = tid; ss < 769; ss += 256) {
        float d = sqrtf((float)ss);
        valid[ss] = ((fmodf(d, fd) == 0.0f) || (ss == 0)) ? 1 : 0;
    }
    __syncthreads();

    int base = tid * 128;
    unsigned long long fl0 = 0ull, fl1 = 0ull;
    int ccnt = 0;
    for (int j = 0; j < 128; ++j) {
        int n = base + j;
        int zz = (n >> 10) - 16, yy = ((n >> 5) & 31) - 16, xx = (n & 31) - 16;
        int ss = zz*zz + yy*yy + xx*xx;
        if (valid[ss]) {
            if (j < 64) fl0 |= (1ull << j); else fl1 |= (1ull << (j - 64));
            ccnt++;
        }
    }
    scan[tid] = ccnt;
    __syncthreads();
    for (int off = 1; off < 256; off <<= 1) {
        int v = (tid >= off) ? scan[tid - off] : 0;
        __syncthreads();
        scan[tid] += v;
        __syncthreads();
    }
    int pos = scan[tid] - ccnt;
    for (int j = 0; j < 64; ++j)
        if (fl0 & (1ull << j)) out[pos++] = base + j;
    for (int j = 0; j < 64; ++j)
        if (fl1 & (1ull << j)) out[pos++] = base + 64 + j;
    if (tid == 255) g_M3[bi] = scan[255];
}

// ---------------- fused patch conv + pos embed, dual-layout write --------------
__global__ void __launch_bounds__(256) conv_pos_kernel(
    const float* __restrict__ x,
    const float* __restrict__ W,
    const float* __restrict__ b,
    const float* __restrict__ pos)
{
    __shared__ float S[128 * 68];
    int bid = blockIdx.x;
    int z   = bid >> 3, yq = bid & 7;
    int y0  = yq * 4;
    int n0  = z * 1024 + y0 * 32;
    int tid = threadIdx.x;

    #pragma unroll
    for (int j = 0; j < 8; ++j) {
        int e   = tid + 256 * j;
        int r   = e >> 5;
        int c4  = e & 31;
        const float4* src = (const float4*)(x
            + (size_t)(4*z + (r >> 4)) * 16384
            + (4*y0 + (r & 15)) * 128 + c4 * 4);
        *(float4*)&S[r * 128 + c4 * 4] = *src;
    }
    __syncthreads();

    int ch = tid & 63;
    int tg = tid >> 6;
    float w[64];
    {
        const float4* wp = (const float4*)(W + ch * 64);
        #pragma unroll
        for (int i = 0; i < 16; ++i) {
            float4 t4 = wp[i];
            w[4*i] = t4.x; w[4*i+1] = t4.y; w[4*i+2] = t4.z; w[4*i+3] = t4.w;
        }
    }
    float bv = b[ch];
    float acc[32];
    #pragma unroll
    for (int i = 0; i < 32; ++i) acc[i] = bv;

    #pragma unroll
    for (int k4 = 0; k4 < 16; ++k4) {
        int row = (k4 >> 2) * 16 + tg * 4 + (k4 & 3);
        const float4* Pr = (const float4*)&S[row * 128];
        float wx = w[4*k4], wy = w[4*k4+1], wz2 = w[4*k4+2], ww = w[4*k4+3];
        #pragma unroll
        for (int i = 0; i < 32; ++i) {
            float4 p = Pr[i];
            acc[i] += p.x * wx;
            acc[i] += p.y * wy;
            acc[i] += p.z * wz2;
            acc[i] += p.w * ww;
        }
    }
    __syncthreads();

    #pragma unroll
    for (int i = 0; i < 32; ++i)
        S[(tg * 32 + i) * 68 + ch] = acc[i];
    __syncthreads();

    #pragma unroll
    for (int rep = 0; rep < 32; ++rep) {
        int e  = tid + 256 * rep;
        int cc = e >> 7, t = e & 127;
        float v = S[t * 68 + cc] + pos[cc * NTOK + n0 + t];
        S[t * 68 + cc] = v;
        g_hT[cc * NTOK + n0 + t] = v;
    }
    __syncthreads();

    #pragma unroll
    for (int j = 0; j < 8; ++j) {
        int e  = tid + 256 * j;
        int t  = e >> 4, c4 = e & 15;
        float4 v = *(const float4*)&S[t * 68 + c4 * 4];
        *(float4*)&g_t[(size_t)(n0 + t) * 64 + c4 * 4] = v;
    }
}

// =================== persistent fused attention stack ==========================
// grid = NBLK x 512, dynamic smem. Per dilation: QKV | bar | flash | bar.
// Flash uses GEMM-style register blocking with broadcast layouts.
__global__ void __launch_bounds__(512) fused_attn_kernel(
    const float* __restrict__ qkvw0, const float* __restrict__ qkvb0,
    const float* __restrict__ pw0,   const float* __restrict__ pb0,
    const float* __restrict__ qkvw1, const float* __restrict__ qkvb1,
    const float* __restrict__ pw1,   const float* __restrict__ pb1,
    const float* __restrict__ qkvw2, const float* __restrict__ qkvb2,
    const float* __restrict__ pw2,   const float* __restrict__ pb2)
{
    extern __shared__ float DSM[];
    int tid = threadIdx.x;
    int bid = blockIdx.x;

    const float* QW[3] = {qkvw0, qkvw1, qkvw2};
    const float* QB[3] = {qkvb0, qkvb1, qkvb2};
    const float* PW[3] = {pw0, pw1, pw2};
    const float* PB[3] = {pb0, pb1, pb2};

    for (int di = 0; di < 3; ++di) {
        int M = g_M3[di];
        const int* __restrict__ idx = g_idx3 + di * NTOK;
        int mtiles = (M + 31) >> 5;

        // ---------------- stage: QKV (scale 1/8 folded into Q) -----------------
        {
            float (*Ts)[68] = (float(*)[68])DSM;
            const float* W  = QW[di];
            const float* bb = QB[di];

            int oc   = tid >> 1;
            int half = tid & 1;
            float w[64]; float bv = 0.f;
            if (oc < 192) {
                const float4* wr = (const float4*)(W + oc * 64);
                #pragma unroll
                for (int i = 0; i < 16; ++i) {
                    float4 t4 = wr[i];
                    w[4*i] = t4.x; w[4*i+1] = t4.y;
                    w[4*i+2] = t4.z; w[4*i+3] = t4.w;
                }
                bv = bb[oc];
            }

            for (int mt = bid; mt < mtiles; mt += NBLK) {
                int m0 = mt * 32;
                __syncthreads();
                #pragma unroll
                for (int j = 0; j < 4; ++j) {
                    int e = tid + 512 * j;
                    int ml = e >> 6, k = e & 63;
                    int m = m0 + ml;
                    Ts[ml][k] = (m < M) ? g_t[idx[m] * 64 + k] : 0.f;
                }
                __syncthreads();
                if (oc < 192) {
                    int mmax = min(32, M - m0);
                    #pragma unroll
                    for (int g = 0; g < 2; ++g) {
                        int ml0 = half * 16 + g * 8;
                        float acc[8];
                        #pragma unroll
                        for (int u = 0; u < 8; ++u) acc[u] = bv;
                        #pragma unroll
                        for (int k4 = 0; k4 < 16; ++k4) {
                            #pragma unroll
                            for (int u = 0; u < 8; ++u) {
                                float4 t4 = *(const float4*)&Ts[ml0 + u][k4 * 4];
                                acc[u] += t4.x * w[4*k4];
                                acc[u] += t4.y * w[4*k4+1];
                                acc[u] += t4.z * w[4*k4+2];
                                acc[u] += t4.w * w[4*k4+3];
                            }
                        }
                        #pragma unroll
                        for (int u = 0; u < 8; ++u) {
                            int ml = ml0 + u;
                            if (ml < mmax) {
                                int m = m0 + ml;
                                if      (oc <  64) g_qs[m * 64 + oc]       = acc[u] * 0.125f;
                                else if (oc < 128) g_ks[m * 64 + oc - 64]  = acc[u];
                                else               g_vs[m * 64 + oc - 128] = acc[u];
                            }
                        }
                    }
                }
            }
        }
        grid_bar();

        // ---------- stage: flash attn (register-blocked) + proj + scatter ------
        {
            float (*Ksm)[68] = (float(*)[68])(DSM + OFF_K);
            float (*Vsm)[68] = (float(*)[68])(DSM + OFF_V);
            float (*Ssm)[36] = (float(*)[36])(DSM + OFF_S);   // [key][row]
            float (*Qsm)[68] = (float(*)[68])(DSM + OFF_Q);
            float* corr_s = DSM + OFF_CORR;
            float* linv_s = DSM + OFF_LINV;
            float (*Ysm)[68] = (float(*)[68])(DSM + OFF_K);   // alias K after loop

            // roles
            int kc  = tid >> 3;       // QK: key 0..63
            int rgq = tid & 7;        // QK: row group
            int r   = tid >> 4;       // softmax: row 0..31
            int qq  = tid & 15;       // softmax: lane
            int cg  = tid >> 3;       // PV: channel 0..63
            int rgp = tid & 7;        // PV: row group

            for (int mt = bid; mt < mtiles; mt += NBLK) {
                int m0 = mt * 32;

                // load Q tile (invalid rows duplicate row m0; masked later)
                __syncthreads();
                {
                    int row = tid >> 4, c4 = tid & 15;
                    int m = m0 + row;
                    *(float4*)&Qsm[row][c4 * 4] =
                        *(const float4*)(g_qs + (size_t)(m < M ? m : m0) * 64 + c4 * 4);
                }
                __syncthreads();

                float y0 = 0.f, y1 = 0.f, y2 = 0.f, y3 = 0.f;   // PV accum (4 rows)
                float row_max = -1e30f, row_sum = 0.f;          // softmax stats

                for (int n0 = 0; n0 < M; n0 += 64) {
                    // ---- load K/V tile ----
                    #pragma unroll
                    for (int j = 0; j < 2; ++j) {
                        int e = tid + 512 * j;
                        int nl = e >> 4, k4 = e & 15;
                        int n = n0 + nl;
                        float4 kv = make_float4(0.f, 0.f, 0.f, 0.f);
                        float4 vv = kv;
                        if (n < M) {
                            kv = *(const float4*)(g_ks + n * 64 + k4 * 4);
                            vv = *(const float4*)(g_vs + n * 64 + k4 * 4);
                        }
                        *(float4*)&Ksm[nl][k4 * 4] = kv;
                        *(float4*)&Vsm[nl][k4 * 4] = vv;
                    }
                    __syncthreads();

                    // ---- QK: thread (kc, rgq) -> scores for 4 rows vs key kc --
                    {
                        float s0 = 0.f, s1 = 0.f, s2 = 0.f, s3 = 0.f;
                        #pragma unroll
                        for (int c4 = 0; c4 < 16; ++c4) {
                            float4 kv = *(const float4*)&Ksm[kc][c4 * 4];
                            float4 q0 = *(const float4*)&Qsm[rgq * 4 + 0][c4 * 4];
                            float4 q1 = *(const float4*)&Qsm[rgq * 4 + 1][c4 * 4];
                            float4 q2 = *(const float4*)&Qsm[rgq * 4 + 2][c4 * 4];
                            float4 q3 = *(const float4*)&Qsm[rgq * 4 + 3][c4 * 4];
                            s0 += q0.x*kv.x + q0.y*kv.y + q0.z*kv.z + q0.w*kv.w;
                            s1 += q1.x*kv.x + q1.y*kv.y + q1.z*kv.z + q1.w*kv.w;
                            s2 += q2.x*kv.x + q2.y*kv.y + q2.z*kv.z + q2.w*kv.w;
                            s3 += q3.x*kv.x + q3.y*kv.y + q3.z*kv.z + q3.w*kv.w;
                        }
                        if (n0 + kc >= M) { s0 = s1 = s2 = s3 = -1e30f; }
                        *(float4*)&Ssm[kc][rgq * 4] = make_float4(s0, s1, s2, s3);
                    }
                    __syncthreads();

                    // ---- softmax: thread (r, qq); keys qq+16kk ---------------
                    {
                        float sc[4];
                        float tmax = -1e30f;
                        #pragma unroll
                        for (int kk = 0; kk < 4; ++kk) {
                            sc[kk] = Ssm[qq + 16 * kk][r];
                            tmax = fmaxf(tmax, sc[kk]);
                        }
                        #pragma unroll
                        for (int o = 1; o < 16; o <<= 1)
                            tmax = fmaxf(tmax, __shfl_xor_sync(0xffffffffu, tmax, o));

                        float nmax = fmaxf(row_max, tmax);
                        float corr = __expf(row_max - nmax);
                        float lsum = 0.f;
                        #pragma unroll
                        for (int kk = 0; kk < 4; ++kk) {
                            float p = __expf(sc[kk] - nmax);
                            Ssm[qq + 16 * kk][r] = p;
                            lsum += p;
                        }
                        #pragma unroll
                        for (int o = 1; o < 16; o <<= 1)
                            lsum += __shfl_xor_sync(0xffffffffu, lsum, o);
                        row_sum = row_sum * corr + lsum;
                        row_max = nmax;
                        if (qq == 0) corr_s[r] = corr;
                    }
                    __syncthreads();

                    // ---- PV: thread (cg, rgp): y[4 rows] for channel cg ------
                    {
                        float c0 = corr_s[rgp * 4 + 0];
                        float c1 = corr_s[rgp * 4 + 1];
                        float c2 = corr_s[rgp * 4 + 2];
                        float c3 = corr_s[rgp * 4 + 3];
                        y0 *= c0; y1 *= c1; y2 *= c2; y3 *= c3;
                        #pragma unroll 8
                        for (int nl = 0; nl < 64; ++nl) {
                            float4 p4 = *(const float4*)&Ssm[nl][rgp * 4];
                            float  v  = Vsm[nl][cg];
                            y0 += p4.x * v;
                            y1 += p4.y * v;
                            y2 += p4.z * v;
                            y3 += p4.w * v;
                        }
                    }
                    __syncthreads();
                }

                // final 1/l
                if (qq == 0) linv_s[r] = 1.0f / row_sum;
                __syncthreads();

                // write Y (alias Ksm region)
                {
                    float l0 = linv_s[rgp * 4 + 0];
                    float l1 = linv_s[rgp * 4 + 1];
                    float l2 = linv_s[rgp * 4 + 2];
                    float l3 = linv_s[rgp * 4 + 3];
                    Ysm[rgp * 4 + 0][cg] = y0 * l0;
                    Ysm[rgp * 4 + 1][cg] = y1 * l1;
                    Ysm[rgp * 4 + 2][cg] = y2 * l2;
                    Ysm[rgp * 4 + 3][cg] = y3 * l3;
                }
                __syncthreads();

                // proj + residual + dual scatter
                int oc = tid & 63;
                int rb = tid >> 6;
                float wrow[64];
                {
                    const float4* wr = (const float4*)(PW[di] + oc * 64);
                    #pragma unroll
                    for (int i = 0; i < 16; ++i) {
                        float4 v = wr[i];
                        wrow[4*i] = v.x; wrow[4*i+1] = v.y;
                        wrow[4*i+2] = v.z; wrow[4*i+3] = v.w;
                    }
                }
                float bv = PB[di][oc];
                int mmax = min(32, M - m0);
                for (int rr = rb; rr < mmax; rr += 8) {
                    float a0 = bv;
                    #pragma unroll
                    for (int k4 = 0; k4 < 16; ++k4) {
                        float4 yv = *(const float4*)&Ysm[rr][k4 * 4];
                        a0 += yv.x * wrow[4*k4];
                        a0 += yv.y * wrow[4*k4+1];
                        a0 += yv.z * wrow[4*k4+2];
                        a0 += yv.w * wrow[4*k4+3];
                    }
                    a0 += Ysm[rr][oc];
                    int tok = idx[m0 + rr];
                    g_t [tok * 64 + oc]   = a0;
                    g_hT[oc * NTOK + tok] = a0;
                }
                __syncthreads();
            }
        }
        if (di < 2) grid_bar();
    }
}

// ---------------- trilinear x4 upsample: hT[c][32^3] -> out[c][128^3] ----------
__global__ void __launch_bounds__(256) upsample_kernel(float* __restrict__ out)
{
    const float S = 31.0f / 127.0f;
    int zo  = blockIdx.x;
    int c   = blockIdx.y;
    int tid = threadIdx.x;

    float pz = (float)zo * S;
    int z0 = (int)pz;
    int z1 = min(z0 + 1, 31);
    float wz = pz - (float)z0;

    __shared__ float F[1024];
    __shared__ float R[128][33];

    const float* p0 = g_hT + c * NTOK + z0 * 1024;
    const float* p1 = g_hT + c * NTOK + z1 * 1024;
    #pragma unroll
    for (int j = 0; j < 4; ++j) {
        int i = tid + 256 * j;
        float a = p0[i];
        F[i] = a + wz * (p1[i] - a);
    }
    __syncthreads();

    int w = tid >> 5, lane = tid & 31;

    #pragma unroll
    for (int j = 0; j < 16; ++j) {
        int yo = j * 8 + w;
        float py = (float)yo * S;
        int y0 = (int)py;
        int y1 = min(y0 + 1, 31);
        float wy = py - (float)y0;
        float a = F[y0 * 32 + lane];
        float b = F[y1 * 32 + lane];
        R[yo][lane] = a + wy * (b - a);
    }
    __syncthreads();

    int   x0[4], x1[4];
    float wx[4];
    #pragma unroll
    for (int j = 0; j < 4; ++j) {
        int xo = lane * 4 + j;
        float px = (float)xo * S;
        x0[j] = (int)px;
        x1[j] = min(x0[j] + 1, 31);
        wx[j] = px - (float)x0[j];
    }

    size_t obase = ((size_t)(c * 128 + zo)) * 16384;
    #pragma unroll
    for (int it = 0; it < 16; ++it) {
        int yo = it * 8 + w;
        const float* Rr = &R[yo][0];
        float4 o;
        #pragma unroll
        for (int j = 0; j < 4; ++j) {
            float r0 = Rr[x0[j]];
            (&o.x)[j] = r0 + wx[j] * (Rr[x1[j]] - r0);
        }
        __stcs((float4*)(out + obase + (size_t)yo * 128 + lane * 4), o);
    }
}

// ---------------- launch --------------------------------------------------------
extern "C" void kernel_launch(void* const* d_in, const int* in_sizes, int n_in,
                              void* d_out, int out_size)
{
    const float* x       = (const float*)d_in[0];
    const float* w_patch = (const float*)d_in[1];
    const float* b_patch = (const float*)d_in[2];
    const float* pos     = (const float*)d_in[3];

    cudaFuncSetAttribute(fused_attn_kernel,
                         cudaFuncAttributeMaxDynamicSharedMemorySize, SMEM_BYTES);

    build_idx_kernel<<<3, 256>>>();
    conv_pos_kernel<<<256, 256>>>(x, w_patch, b_patch, pos);

    fused_attn_kernel<<<NBLK, 512, SMEM_BYTES>>>(
        (const float*)d_in[4],  (const float*)d_in[5],
        (const float*)d_in[6],  (const float*)d_in[7],
        (const float*)d_in[8],  (const float*)d_in[9],
        (const float*)d_in[10], (const float*)d_in[11],
        (const float*)d_in[12], (const float*)d_in[13],
        (const float*)d_in[14], (const float*)d_in[15]);

    upsample_kernel<<<dim3(128, 64), 256>>>((float*)d_out);
}

// round 14
// speedup vs baseline: 1.2836x; 1.2836x over previous
#include <cuda_runtime.h>
#include <math.h>

#define NTOK 32768
#define NBLK 12              // persistent grid for attn stack (all resident)
#define MCAP 304             // max tokens per dilation (actual: 280/64/139)

// flash/qkv dynamic smem offsets (floats)
#define KOFF   0             // K   [304][68]
#define VOFF   20672         // V   [304][68]
#define POFF   41344         // P   [32][308]  (Y [32][68] aliases after sync)
#define QOFF   51200         // Q   [32][68]
#define WTOFF  53376         // projW^T [64][68]
#define SMEM_FLOATS 57728
#define SMEM_BYTES (SMEM_FLOATS * 4)   // 230,912 B
// qkv-stage aliases (inside K region, dead between stages)
#define WQOFF  0             // qkv W^T [64][196]
#define BOFF   12544         // qkv bias [192]
#define TSOFF  12800         // gathered tokens [32][68]

// ---------------- scratch (static device memory; no allocation) ----------------
__device__ float g_t  [NTOK * 64];
__device__ float g_hT [NTOK * 64];
__device__ float g_qs [NTOK * 64];
__device__ float g_ks [NTOK * 64];
__device__ float g_vs [NTOK * 64];
__device__ int   g_idx3[3 * NTOK];
__device__ int   g_M3[3];
__device__ unsigned g_gen = 0;
__device__ unsigned g_arrive = 0;

// ---------------- software grid barrier ----------------------------------------
__device__ __forceinline__ void grid_bar()
{
    __syncthreads();
    if (threadIdx.x == 0) {
        __threadfence();
        unsigned gen = *(volatile unsigned*)&g_gen;
        if (atomicAdd(&g_arrive, 1u) == NBLK - 1) {
            g_arrive = 0;
            __threadfence();
            atomicAdd(&g_gen, 1u);
        } else {
            while (*(volatile unsigned*)&g_gen == gen) {}
        }
        __threadfence();
    }
    __syncthreads();
}

// ---------------- dilation index build (ss-table, bit-exact vs numpy) ----------
__global__ void __launch_bounds__(256) build_idx_kernel()
{
    __shared__ unsigned char valid[769];
    __shared__ int scan[256];
    int bi  = blockIdx.x;
    int dil = (bi == 0) ? 2 : (bi == 1) ? 4 : 6;
    int* out = g_idx3 + bi * NTOK;
    int tid  = threadIdx.x;
    float fd = (float)dil;

    for (int ss = tid; ss < 769; ss += 256) {
        float d = sqrtf((float)ss);
        valid[ss] = ((fmodf(d, fd) == 0.0f) || (ss == 0)) ? 1 : 0;
    }
    __syncthreads();

    int base = tid * 128;
    unsigned long long fl0 = 0ull, fl1 = 0ull;
    int ccnt = 0;
    for (int j = 0; j < 128; ++j) {
        int n = base + j;
        int zz = (n >> 10) - 16, yy = ((n >> 5) & 31) - 16, xx = (n & 31) - 16;
        int ss = zz*zz + yy*yy + xx*xx;
        if (valid[ss]) {
            if (j < 64) fl0 |= (1ull << j); else fl1 |= (1ull << (j - 64));
            ccnt++;
        }
    }
    scan[tid] = ccnt;
    __syncthreads();
    for (int off = 1; off < 256; off <<= 1) {
        int v = (tid >= off) ? scan[tid - off] : 0;
        __syncthreads();
        scan[tid] += v;
        __syncthreads();
    }
    int pos = scan[tid] - ccnt;
    for (int j = 0; j < 64; ++j)
        if (fl0 & (1ull << j)) out[pos++] = base + j;
    for (int j = 0; j < 64; ++j)
        if (fl1 & (1ull << j)) out[pos++] = base + 64 + j;
    if (tid == 255) g_M3[bi] = scan[255];
}

// ---------------- fused patch conv + pos embed, dual-layout write --------------
__global__ void __launch_bounds__(256) conv_pos_kernel(
    const float* __restrict__ x,
    const float* __restrict__ W,
    const float* __restrict__ b,
    const float* __restrict__ pos)
{
    __shared__ float S[128 * 68];
    int bid = blockIdx.x;
    int z   = bid >> 3, yq = bid & 7;
    int y0  = yq * 4;
    int n0  = z * 1024 + y0 * 32;
    int tid = threadIdx.x;

    #pragma unroll
    for (int j = 0; j < 8; ++j) {
        int e   = tid + 256 * j;
        int r   = e >> 5;
        int c4  = e & 31;
        const float4* src = (const float4*)(x
            + (size_t)(4*z + (r >> 4)) * 16384
            + (4*y0 + (r & 15)) * 128 + c4 * 4);
        *(float4*)&S[r * 128 + c4 * 4] = *src;
    }
    __syncthreads();

    int ch = tid & 63;
    int tg = tid >> 6;
    float w[64];
    {
        const float4* wp = (const float4*)(W + ch * 64);
        #pragma unroll
        for (int i = 0; i < 16; ++i) {
            float4 t4 = wp[i];
            w[4*i] = t4.x; w[4*i+1] = t4.y; w[4*i+2] = t4.z; w[4*i+3] = t4.w;
        }
    }
    float bv = b[ch];
    float acc[32];
    #pragma unroll
    for (int i = 0; i < 32; ++i) acc[i] = bv;

    #pragma unroll
    for (int k4 = 0; k4 < 16; ++k4) {
        int row = (k4 >> 2) * 16 + tg * 4 + (k4 & 3);
        const float4* Pr = (const float4*)&S[row * 128];
        float wx = w[4*k4], wy = w[4*k4+1], wz2 = w[4*k4+2], ww = w[4*k4+3];
        #pragma unroll
        for (int i = 0; i < 32; ++i) {
            float4 p = Pr[i];
            acc[i] += p.x * wx;
            acc[i] += p.y * wy;
            acc[i] += p.z * wz2;
            acc[i] += p.w * ww;
        }
    }
    __syncthreads();

    #pragma unroll
    for (int i = 0; i < 32; ++i)
        S[(tg * 32 + i) * 68 + ch] = acc[i];
    __syncthreads();

    #pragma unroll
    for (int rep = 0; rep < 32; ++rep) {
        int e  = tid + 256 * rep;
        int cc = e >> 7, t = e & 127;
        float v = S[t * 68 + cc] + pos[cc * NTOK + n0 + t];
        S[t * 68 + cc] = v;
        g_hT[cc * NTOK + n0 + t] = v;
    }
    __syncthreads();

    #pragma unroll
    for (int j = 0; j < 8; ++j) {
        int e  = tid + 256 * j;
        int t  = e >> 4, c4 = e & 15;
        float4 v = *(const float4*)&S[t * 68 + c4 * 4];
        *(float4*)&g_t[(size_t)(n0 + t) * 64 + c4 * 4] = v;
    }
}

// =================== persistent fused attention stack ==========================
// grid = NBLK x 1024, 226KB dynamic smem. Per dilation:
//   QKV (W^T in smem) | bar | full-K-resident flash + proj + scatter | bar
__global__ void __launch_bounds__(1024, 1) fused_attn_kernel(
    const float* __restrict__ qkvw0, const float* __restrict__ qkvb0,
    const float* __restrict__ pw0,   const float* __restrict__ pb0,
    const float* __restrict__ qkvw1, const float* __restrict__ qkvb1,
    const float* __restrict__ pw1,   const float* __restrict__ pb1,
    const float* __restrict__ qkvw2, const float* __restrict__ qkvb2,
    const float* __restrict__ pw2,   const float* __restrict__ pb2)
{
    extern __shared__ float S[];
    int tid = threadIdx.x;
    int bid = blockIdx.x;

    const float* QW[3] = {qkvw0, qkvw1, qkvw2};
    const float* QB[3] = {qkvb0, qkvb1, qkvb2};
    const float* PW[3] = {pw0, pw1, pw2};
    const float* PB[3] = {pb0, pb1, pb2};

    for (int di = 0; di < 3; ++di) {
        int M = g_M3[di];
        const int* __restrict__ idx = g_idx3 + di * NTOK;
        int mtiles = (M + 31) >> 5;

        // ---------------- stage: QKV (scale 1/8 folded into Q) -----------------
        if (bid < mtiles) {
            // load qkv W^T [k][oc] (stride 196) + bias
            for (int j = 0; j < 12; ++j) {
                int e = tid + 1024 * j;                // 12288 elements
                int oc = e >> 6, k = e & 63;
                S[WQOFF + k * 196 + oc] = QW[di][e];
            }
            if (tid < 192) S[BOFF + tid] = QB[di][tid];
            __syncthreads();

            int oc = tid & 255;          // <192 active
            int rg = tid >> 8;           // row group 0..3 (8 rows each)

            for (int mt = bid; mt < mtiles; mt += NBLK) {
                int m0 = mt * 32;
                __syncthreads();
                #pragma unroll
                for (int j = 0; j < 2; ++j) {
                    int e = tid + 1024 * j;            // 2048 elements
                    int ml = e >> 6, k = e & 63;
                    int m = m0 + ml;
                    S[TSOFF + ml * 68 + k] = (m < M) ? g_t[idx[m] * 64 + k] : 0.f;
                }
                __syncthreads();

                if (oc < 192) {
                    float acc[8];
                    float bv = S[BOFF + oc];
                    #pragma unroll
                    for (int u = 0; u < 8; ++u) acc[u] = bv;
                    #pragma unroll
                    for (int k4 = 0; k4 < 16; ++k4) {
                        float w0 = S[WQOFF + (4*k4+0) * 196 + oc];
                        float w1 = S[WQOFF + (4*k4+1) * 196 + oc];
                        float w2 = S[WQOFF + (4*k4+2) * 196 + oc];
                        float w3 = S[WQOFF + (4*k4+3) * 196 + oc];
                        #pragma unroll
                        for (int u = 0; u < 8; ++u) {
                            float4 t4 = *(const float4*)&S[TSOFF + (rg*8+u) * 68 + k4 * 4];
                            acc[u] += t4.x * w0;
                            acc[u] += t4.y * w1;
                            acc[u] += t4.z * w2;
                            acc[u] += t4.w * w3;
                        }
                    }
                    int mmax = min(32, M - m0);
                    #pragma unroll
                    for (int u = 0; u < 8; ++u) {
                        int ml = rg * 8 + u;
                        if (ml < mmax) {
                            int m = m0 + ml;
                            if      (oc <  64) g_qs[m * 64 + oc]       = acc[u] * 0.125f;
                            else if (oc < 128) g_ks[m * 64 + oc - 64]  = acc[u];
                            else               g_vs[m * 64 + oc - 128] = acc[u];
                        }
                    }
                }
            }
        }
        grid_bar();

        // ---------- stage: full-K-resident flash + proj + resid + scatter ------
        if (bid < mtiles) {
            // load ALL K/V for this dilation + proj W^T (once per block)
            {
                int nslots = M * 16;                   // float4 slots per matrix
                for (int e = tid; e < nslots; e += 1024) {
                    int nl = e >> 4, c4 = e & 15;
                    *(float4*)&S[KOFF + nl * 68 + c4 * 4] =
                        *(const float4*)(g_ks + nl * 64 + c4 * 4);
                    *(float4*)&S[VOFF + nl * 68 + c4 * 4] =
                        *(const float4*)(g_vs + nl * 64 + c4 * 4);
                }
                #pragma unroll
                for (int j = 0; j < 4; ++j) {
                    int e = tid + 1024 * j;            // 4096 elements
                    int oc = e >> 6, k = e & 63;
                    S[WTOFF + k * 68 + oc] = PW[di][e];
                }
            }
            __syncthreads();

            int r  = tid >> 5;        // query row 0..31 (warp == row)
            int qq = tid & 31;        // lane
            int ch = 2 * qq;          // PV: channels ch, ch+1

            for (int mt = bid; mt < mtiles; mt += NBLK) {
                int m0 = mt * 32;
                __syncthreads();                       // prior proj reads done
                if (tid < 512) {
                    int row = tid >> 4, c4 = tid & 15;
                    int m = m0 + row;
                    *(float4*)&S[QOFF + row * 68 + c4 * 4] =
                        *(const float4*)(g_qs + (size_t)(m < M ? m : m0) * 64 + c4 * 4);
                }
                __syncthreads();

                // ---- QK: lane qq -> keys qq + 32*kk ----
                float sc[10];
                int   nlc[10];
                #pragma unroll
                for (int kk = 0; kk < 10; ++kk) {
                    int nl = qq + 32 * kk;
                    nlc[kk] = (nl < M) ? nl : 0;
                    sc[kk]  = 0.f;
                }
                const float* Qr = S + QOFF + r * 68;
                #pragma unroll
                for (int c4 = 0; c4 < 16; ++c4) {
                    float4 q4 = *(const float4*)(Qr + c4 * 4);
                    #pragma unroll
                    for (int kk = 0; kk < 10; ++kk) {
                        float4 k4 = *(const float4*)&S[KOFF + nlc[kk] * 68 + c4 * 4];
                        sc[kk] += q4.x * k4.x;
                        sc[kk] += q4.y * k4.y;
                        sc[kk] += q4.z * k4.z;
                        sc[kk] += q4.w * k4.w;
                    }
                }

                // ---- single-pass softmax over all M keys ----
                float tmax = -1e30f;
                #pragma unroll
                for (int kk = 0; kk < 10; ++kk) {
                    if (qq + 32 * kk >= M) sc[kk] = -1e30f;
                    tmax = fmaxf(tmax, sc[kk]);
                }
                #pragma unroll
                for (int o = 1; o < 32; o <<= 1)
                    tmax = fmaxf(tmax, __shfl_xor_sync(0xffffffffu, tmax, o));

                float lsum = 0.f;
                #pragma unroll
                for (int kk = 0; kk < 10; ++kk) {
                    int nl = qq + 32 * kk;
                    if (nl < M) {
                        float p = __expf(sc[kk] - tmax);
                        S[POFF + r * 308 + nl] = p;
                        lsum += p;
                    }
                }
                #pragma unroll
                for (int o = 1; o < 32; o <<= 1)
                    lsum += __shfl_xor_sync(0xffffffffu, lsum, o);
                float inv = 1.0f / lsum;
                __syncwarp();

                // ---- PV: warp reads its own P row; channels ch, ch+1 ----
                float y0 = 0.f, y1 = 0.f;
                const float* Pr = S + POFF + r * 308;
                const float* Vb = S + VOFF + ch;
                int nl = 0;
                #pragma unroll 4
                for (; nl + 4 <= M; nl += 4) {
                    #pragma unroll
                    for (int i = 0; i < 4; ++i) {
                        float p = Pr[nl + i];
                        y0 += p * Vb[(nl + i) * 68];
                        y1 += p * Vb[(nl + i) * 68 + 1];
                    }
                }
                for (; nl < M; ++nl) {
                    float p = Pr[nl];
                    y0 += p * Vb[nl * 68];
                    y1 += p * Vb[nl * 68 + 1];
                }

                __syncthreads();                       // all P reads done
                // Y aliases P region, stride 68
                S[POFF + r * 68 + ch]     = y0 * inv;
                S[POFF + r * 68 + ch + 1] = y1 * inv;
                __syncthreads();

                // ---- proj + residual + dual scatter ----
                int oc = tid & 63;
                int rb = tid >> 6;                     // 0..15
                float bv = PB[di][oc];
                int mmax = min(32, M - m0);
                for (int rr = rb; rr < mmax; rr += 16) {
                    float a = bv;
                    #pragma unroll
                    for (int c4 = 0; c4 < 16; ++c4) {
                        float4 y4 = *(const float4*)&S[POFF + rr * 68 + c4 * 4];
                        a += y4.x * S[WTOFF + (4*c4+0) * 68 + oc];
                        a += y4.y * S[WTOFF + (4*c4+1) * 68 + oc];
                        a += y4.z * S[WTOFF + (4*c4+2) * 68 + oc];
                        a += y4.w * S[WTOFF + (4*c4+3) * 68 + oc];
                    }
                    a += S[POFF + rr * 68 + oc];
                    int tok = idx[m0 + rr];
                    g_t [tok * 64 + oc]   = a;
                    g_hT[oc * NTOK + tok] = a;
                }
            }
        }
        if (di < 2) grid_bar();
    }
}

// ---------------- trilinear x4 upsample: hT[c][32^3] -> out[c][128^3] ----------
__global__ void __launch_bounds__(256) upsample_kernel(float* __restrict__ out)
{
    const float S = 31.0f / 127.0f;
    int zo  = blockIdx.x;
    int c   = blockIdx.y;
    int tid = threadIdx.x;

    float pz = (float)zo * S;
    int z0 = (int)pz;
    int z1 = min(z0 + 1, 31);
    float wz = pz - (float)z0;

    __shared__ float F[1024];
    __shared__ float R[128][33];

    const float* p0 = g_hT + c * NTOK + z0 * 1024;
    const float* p1 = g_hT + c * NTOK + z1 * 1024;
    #pragma unroll
    for (int j = 0; j < 4; ++j) {
        int i = tid + 256 * j;
        float a = p0[i];
        F[i] = a + wz * (p1[i] - a);
    }
    __syncthreads();

    int w = tid >> 5, lane = tid & 31;

    #pragma unroll
    for (int j = 0; j < 16; ++j) {
        int yo = j * 8 + w;
        float py = (float)yo * S;
        int y0 = (int)py;
        int y1 = min(y0 + 1, 31);
        float wy = py - (float)y0;
        float a = F[y0 * 32 + lane];
        float b = F[y1 * 32 + lane];
        R[yo][lane] = a + wy * (b - a);
    }
    __syncthreads();

    int   x0[4], x1[4];
    float wx[4];
    #pragma unroll
    for (int j = 0; j < 4; ++j) {
        int xo = lane * 4 + j;
        float px = (float)xo * S;
        x0[j] = (int)px;
        x1[j] = min(x0[j] + 1, 31);
        wx[j] = px - (float)x0[j];
    }

    size_t obase = ((size_t)(c * 128 + zo)) * 16384;
    #pragma unroll
    for (int it = 0; it < 16; ++it) {
        int yo = it * 8 + w;
        const float* Rr = &R[yo][0];
        float4 o;
        #pragma unroll
        for (int j = 0; j < 4; ++j) {
            float r0 = Rr[x0[j]];
            (&o.x)[j] = r0 + wx[j] * (Rr[x1[j]] - r0);
        }
        __stcs((float4*)(out + obase + (size_t)yo * 128 + lane * 4), o);
    }
}

// ---------------- launch --------------------------------------------------------
extern "C" void kernel_launch(void* const* d_in, const int* in_sizes, int n_in,
                              void* d_out, int out_size)
{
    const float* x       = (const float*)d_in[0];
    const float* w_patch = (const float*)d_in[1];
    const float* b_patch = (const float*)d_in[2];
    const float* pos     = (const float*)d_in[3];

    cudaFuncSetAttribute(fused_attn_kernel,
                         cudaFuncAttributeMaxDynamicSharedMemorySize, SMEM_BYTES);

    build_idx_kernel<<<3, 256>>>();
    conv_pos_kernel<<<256, 256>>>(x, w_patch, b_patch, pos);

    fused_attn_kernel<<<NBLK, 1024, SMEM_BYTES>>>(
        (const float*)d_in[4],  (const float*)d_in[5],
        (const float*)d_in[6],  (const float*)d_in[7],
        (const float*)d_in[8],  (const float*)d_in[9],
        (const float*)d_in[10], (const float*)d_in[11],
        (const float*)d_in[12], (const float*)d_in[13],
        (const float*)d_in[14], (const float*)d_in[15]);

    upsample_kernel<<<dim3(128, 64), 256>>>((float*)d_out);
}